// round 1
// baseline (speedup 1.0000x reference)
#include <cuda_runtime.h>
#include <math.h>

#define D_MODEL 1024
#define S_LEN   2048
#define NHEAD   16
#define HDIM    64
#define MAXB    4

// scratch (allocation-free rule: __device__ globals)
__device__ float g_Q [MAXB * S_LEN * D_MODEL];
__device__ float g_K [MAXB * S_LEN * D_MODEL];
__device__ float g_V [MAXB * S_LEN * D_MODEL];
__device__ float g_AO[MAXB * S_LEN * D_MODEL];

// ---------------------------------------------------------------------------
// C[M,N] = A[M,K] @ W[N,K]^T   (both operands K-contiguous, "NT" GEMM)
// 128x128 block tile, BK=16, 8x8 micro-tile, 256 threads.
// ---------------------------------------------------------------------------
__global__ __launch_bounds__(256) void gemm_nt(
    const float* __restrict__ A, const float* __restrict__ W,
    float* __restrict__ C, int M, int N, int K)
{
    __shared__ float As[16][132];  // [k][m], +4 pad keeps float4 alignment
    __shared__ float Ws[16][132];  // [k][n]

    const int tid = threadIdx.x;
    const int m0 = blockIdx.y * 128;
    const int n0 = blockIdx.x * 128;
    const int ty = tid >> 4;        // 0..15
    const int tx = tid & 15;        // 0..15

    float acc[8][8] = {};

    for (int k0 = 0; k0 < K; k0 += 16) {
        #pragma unroll
        for (int it = 0; it < 2; ++it) {
            int idx = tid + it * 256;
            int lr = idx >> 2;            // 0..127
            int lc = (idx & 3) << 2;      // 0,4,8,12
            float4 a = *(const float4*)(A + (size_t)(m0 + lr) * K + k0 + lc);
            float4 w = *(const float4*)(W + (size_t)(n0 + lr) * K + k0 + lc);
            As[lc + 0][lr] = a.x; As[lc + 1][lr] = a.y;
            As[lc + 2][lr] = a.z; As[lc + 3][lr] = a.w;
            Ws[lc + 0][lr] = w.x; Ws[lc + 1][lr] = w.y;
            Ws[lc + 2][lr] = w.z; Ws[lc + 3][lr] = w.w;
        }
        __syncthreads();

        #pragma unroll
        for (int kk = 0; kk < 16; ++kk) {
            float4 a0 = *(const float4*)&As[kk][ty * 8];
            float4 a1 = *(const float4*)&As[kk][ty * 8 + 4];
            float4 w0 = *(const float4*)&Ws[kk][tx * 8];
            float4 w1 = *(const float4*)&Ws[kk][tx * 8 + 4];
            float av[8] = {a0.x, a0.y, a0.z, a0.w, a1.x, a1.y, a1.z, a1.w};
            float wv[8] = {w0.x, w0.y, w0.z, w0.w, w1.x, w1.y, w1.z, w1.w};
            #pragma unroll
            for (int i = 0; i < 8; ++i)
                #pragma unroll
                for (int j = 0; j < 8; ++j)
                    acc[i][j] += av[i] * wv[j];
        }
        __syncthreads();
    }

    #pragma unroll
    for (int i = 0; i < 8; ++i) {
        int row = m0 + ty * 8 + i;
        float4 c0 = {acc[i][0], acc[i][1], acc[i][2], acc[i][3]};
        float4 c1 = {acc[i][4], acc[i][5], acc[i][6], acc[i][7]};
        *(float4*)(C + (size_t)row * N + n0 + tx * 8)     = c0;
        *(float4*)(C + (size_t)row * N + n0 + tx * 8 + 4) = c1;
    }
}

// ---------------------------------------------------------------------------
// RoPE in-place on Q and K. One thread per even/odd pair, same indexing as ref:
// angle = pos * theta^{-(2i)/64}, pairs are interleaved (cols 2i, 2i+1).
// ---------------------------------------------------------------------------
__global__ void rope_kernel(float* __restrict__ Q, float* __restrict__ K, int npairs)
{
    int p = blockIdx.x * blockDim.x + threadIdx.x;
    if (p >= npairs) return;
    int row = p >> 9;            // /512 pairs per row
    int pr  = p & 511;
    int i   = pr & 31;           // pair index within head (0..31)
    int s   = row & (S_LEN - 1); // sequence position
    float inv = expf(-logf(10000.0f) * ((float)i / 32.0f));
    float ang = (float)s * inv;
    float sn, cs;
    sincosf(ang, &sn, &cs);
    size_t idx = (size_t)row * D_MODEL + (size_t)(pr >> 5) * HDIM + 2 * i;
    float qe = Q[idx], qo = Q[idx + 1];
    Q[idx]     = qe * cs - qo * sn;
    Q[idx + 1] = qe * sn + qo * cs;
    float ke = K[idx], ko = K[idx + 1];
    K[idx]     = ke * cs - ko * sn;
    K[idx + 1] = ke * sn + ko * cs;
}

// ---------------------------------------------------------------------------
// Causal flash attention. One block = (b, h, 128 q-rows). K-tiles of 64.
// Q/K/S stored transposed in smem so all hot-loop reads are LDS.128.
// ---------------------------------------------------------------------------
__global__ __launch_bounds__(256) void flash_kernel(
    const float* __restrict__ Qg, const float* __restrict__ Kg,
    const float* __restrict__ Vg, float* __restrict__ Og)
{
    extern __shared__ float sm[];
    float* Qt   = sm;                 // [64 d][132]  (128 rows + pad)
    float* Kt   = Qt + 64 * 132;      // [64 d][68]   (64 keys + pad)
    float* Vs   = Kt + 64 * 68;       // [64 key][68] (64 d + pad)
    float* Ss   = Vs + 64 * 68;       // [64 key][132](128 rows + pad)
    float* rmax = Ss + 64 * 132;      // [128]
    float* rsum = rmax + 128;         // [128]
    float* ralp = rsum + 128;         // [128]

    const int tid = threadIdx.x;
    const int b = blockIdx.z, h = blockIdx.y;
    const int q0 = blockIdx.x * 128;
    const int ty = tid >> 4;   // 0..15 -> rows ty*8..
    const int tx = tid & 15;   // 0..15 -> cols tx*4..

    const float* Qb = Qg + (size_t)(b * S_LEN + q0) * D_MODEL + h * HDIM;

    // load Q tile transposed: Qt[d][row]
    #pragma unroll
    for (int it = 0; it < 8; ++it) {
        int idx = tid + it * 256;
        int r = idx >> 4, c4 = (idx & 15) << 2;
        float4 v = *(const float4*)(Qb + (size_t)r * D_MODEL + c4);
        Qt[(c4 + 0) * 132 + r] = v.x;
        Qt[(c4 + 1) * 132 + r] = v.y;
        Qt[(c4 + 2) * 132 + r] = v.z;
        Qt[(c4 + 3) * 132 + r] = v.w;
    }
    if (tid < 128) { rmax[tid] = -1e30f; rsum[tid] = 0.0f; }

    float o[8][4] = {};
    const int jend = 2 * blockIdx.x + 2;   // causal: tiles up to the diagonal

    for (int j = 0; j < jend; ++j) {
        const int k0 = j * 64;
        const float* Kb = Kg + (size_t)(b * S_LEN + k0) * D_MODEL + h * HDIM;
        const float* Vb = Vg + (size_t)(b * S_LEN + k0) * D_MODEL + h * HDIM;

        __syncthreads();   // previous-iter consumers done (also covers Q load on iter 0)
        #pragma unroll
        for (int it = 0; it < 4; ++it) {
            int idx = tid + it * 256;
            int r = idx >> 4, c4 = (idx & 15) << 2;
            float4 kv = *(const float4*)(Kb + (size_t)r * D_MODEL + c4);
            Kt[(c4 + 0) * 68 + r] = kv.x;
            Kt[(c4 + 1) * 68 + r] = kv.y;
            Kt[(c4 + 2) * 68 + r] = kv.z;
            Kt[(c4 + 3) * 68 + r] = kv.w;
            float4 vv = *(const float4*)(Vb + (size_t)r * D_MODEL + c4);
            *(float4*)&Vs[r * 68 + c4] = vv;
        }
        __syncthreads();

        // S = Q @ K^T (tile 128x64), micro-tile 8x4
        float s[8][4] = {};
        #pragma unroll 8
        for (int kk = 0; kk < 64; ++kk) {
            float4 q0v = *(const float4*)&Qt[kk * 132 + ty * 8];
            float4 q1v = *(const float4*)&Qt[kk * 132 + ty * 8 + 4];
            float4 kv  = *(const float4*)&Kt[kk * 68  + tx * 4];
            float qv[8] = {q0v.x, q0v.y, q0v.z, q0v.w, q1v.x, q1v.y, q1v.z, q1v.w};
            float kvv[4] = {kv.x, kv.y, kv.z, kv.w};
            #pragma unroll
            for (int i = 0; i < 8; ++i)
                #pragma unroll
                for (int jj = 0; jj < 4; ++jj)
                    s[i][jj] += qv[i] * kvv[jj];
        }

        const float scale = 0.125f;  // 1/sqrt(64)
        const bool need_mask = (k0 + 63 > q0);
        #pragma unroll
        for (int i = 0; i < 8; ++i) {
            #pragma unroll
            for (int jj = 0; jj < 4; ++jj) {
                float val = s[i][jj] * scale;
                if (need_mask && (k0 + tx * 4 + jj > q0 + ty * 8 + i)) val = -1e30f;
                Ss[(tx * 4 + jj) * 132 + ty * 8 + i] = val;   // store transposed [key][row]
            }
        }
        __syncthreads();

        // online softmax: one thread per q-row
        if (tid < 128) {
            int r = tid;
            float mo = rmax[r];
            float mt = -1e30f;
            for (int c = 0; c < 64; ++c) mt = fmaxf(mt, Ss[c * 132 + r]);
            float mn = fmaxf(mo, mt);
            float al = __expf(mo - mn);
            float ps = 0.0f;
            for (int c = 0; c < 64; ++c) {
                float pv = __expf(Ss[c * 132 + r] - mn);
                Ss[c * 132 + r] = pv;
                ps += pv;
            }
            rmax[r] = mn;
            rsum[r] = rsum[r] * al + ps;
            ralp[r] = al;
        }
        __syncthreads();

        // O = O*alpha + P @ V
        #pragma unroll
        for (int i = 0; i < 8; ++i) {
            float al = ralp[ty * 8 + i];
            #pragma unroll
            for (int jj = 0; jj < 4; ++jj) o[i][jj] *= al;
        }
        #pragma unroll 8
        for (int kk = 0; kk < 64; ++kk) {
            float4 p0 = *(const float4*)&Ss[kk * 132 + ty * 8];
            float4 p1 = *(const float4*)&Ss[kk * 132 + ty * 8 + 4];
            float4 vv = *(const float4*)&Vs[kk * 68  + tx * 4];
            float pv[8] = {p0.x, p0.y, p0.z, p0.w, p1.x, p1.y, p1.z, p1.w};
            float vvv[4] = {vv.x, vv.y, vv.z, vv.w};
            #pragma unroll
            for (int i = 0; i < 8; ++i)
                #pragma unroll
                for (int jj = 0; jj < 4; ++jj)
                    o[i][jj] += pv[i] * vvv[jj];
        }
    }

    // epilogue: normalize and write [B,S,H,dh] -> flat [B*S, D]
    float* Ob = Og + (size_t)(b * S_LEN + q0) * D_MODEL + h * HDIM;
    #pragma unroll
    for (int i = 0; i < 8; ++i) {
        float inv = 1.0f / rsum[ty * 8 + i];
        float4 w = {o[i][0] * inv, o[i][1] * inv, o[i][2] * inv, o[i][3] * inv};
        *(float4*)(Ob + (size_t)(ty * 8 + i) * D_MODEL + tx * 4) = w;
    }
}

// ---------------------------------------------------------------------------
extern "C" void kernel_launch(void* const* d_in, const int* in_sizes, int n_in,
                              void* d_out, int out_size)
{
    const float* x  = (const float*)d_in[0];
    const float* qw = (const float*)d_in[1];
    const float* kw = (const float*)d_in[2];
    const float* vw = (const float*)d_in[3];
    const float* ow = (const float*)d_in[4];

    const int M = in_sizes[0] / D_MODEL;   // B * S = 8192
    const int B = M / S_LEN;

    void *pq, *pk, *pv, *pa;
    cudaGetSymbolAddress(&pq, g_Q);
    cudaGetSymbolAddress(&pk, g_K);
    cudaGetSymbolAddress(&pv, g_V);
    cudaGetSymbolAddress(&pa, g_AO);
    float* Qp = (float*)pq;
    float* Kp = (float*)pk;
    float* Vp = (float*)pv;
    float* AOp = (float*)pa;

    dim3 ggrid(D_MODEL / 128, M / 128);
    gemm_nt<<<ggrid, 256>>>(x, qw, Qp, M, D_MODEL, D_MODEL);
    gemm_nt<<<ggrid, 256>>>(x, kw, Kp, M, D_MODEL, D_MODEL);
    gemm_nt<<<ggrid, 256>>>(x, vw, Vp, M, D_MODEL, D_MODEL);

    int npairs = M * (D_MODEL / 2);
    rope_kernel<<<(npairs + 255) / 256, 256>>>(Qp, Kp, npairs);

    const int FLASH_SMEM = (64 * 132 + 64 * 68 + 64 * 68 + 64 * 132 + 3 * 128) * 4;
    cudaFuncSetAttribute(flash_kernel, cudaFuncAttributeMaxDynamicSharedMemorySize, FLASH_SMEM);
    dim3 fgrid(S_LEN / 128, NHEAD, B);
    flash_kernel<<<fgrid, 256, FLASH_SMEM>>>(Qp, Kp, Vp, AOp);

    gemm_nt<<<ggrid, 256>>>(AOp, ow, (float*)d_out, M, D_MODEL, D_MODEL);
}

// round 3
// speedup vs baseline: 1.5016x; 1.5016x over previous
#include <cuda_runtime.h>
#include <cuda_bf16.h>
#include <math.h>
#include <stdint.h>

#define D_MODEL 1024
#define S_LEN   2048
#define NHEAD   16
#define HDIM    64
#define MAXB    4
#define MMAX    (MAXB * S_LEN)

// ---------------- scratch (__device__ globals; no allocs allowed) ----------
__device__ float g_Q [MMAX * D_MODEL];
__device__ float g_K [MMAX * D_MODEL];
__device__ float g_V [MMAX * D_MODEL];
__device__ float g_AO[MMAX * D_MODEL];
__device__ __nv_bfloat16 g_xh [MMAX * D_MODEL];
__device__ __nv_bfloat16 g_xl [MMAX * D_MODEL];
__device__ __nv_bfloat16 g_aoh[MMAX * D_MODEL];
__device__ __nv_bfloat16 g_aol[MMAX * D_MODEL];
__device__ __nv_bfloat16 g_wh [4 * D_MODEL * D_MODEL];
__device__ __nv_bfloat16 g_wl [4 * D_MODEL * D_MODEL];

// ---------------- helpers ----------------------------------------------------
__device__ __forceinline__ uint32_t smem_u32(const void* p) {
    uint32_t a;
    asm("{ .reg .u64 t; cvta.to.shared.u64 t, %1; cvt.u32.u64 %0, t; }" : "=r"(a) : "l"(p));
    return a;
}
__device__ __forceinline__ void cp_async16(uint32_t saddr, const void* gptr) {
    asm volatile("cp.async.cg.shared.global [%0], [%1], 16;" :: "r"(saddr), "l"(gptr));
}
__device__ __forceinline__ void ldmx4(uint32_t* r, uint32_t addr) {
    asm volatile("ldmatrix.sync.aligned.m8n8.x4.shared.b16 {%0,%1,%2,%3}, [%4];"
                 : "=r"(r[0]), "=r"(r[1]), "=r"(r[2]), "=r"(r[3]) : "r"(addr));
}
__device__ __forceinline__ void mma16816(float* d, const uint32_t* a, const uint32_t* b) {
    asm volatile("mma.sync.aligned.m16n8k16.row.col.f32.bf16.bf16.f32 "
                 "{%0,%1,%2,%3}, {%4,%5,%6,%7}, {%8,%9}, {%0,%1,%2,%3};"
                 : "+f"(d[0]), "+f"(d[1]), "+f"(d[2]), "+f"(d[3])
                 : "r"(a[0]), "r"(a[1]), "r"(a[2]), "r"(a[3]), "r"(b[0]), "r"(b[1]));
}

// ---------------- split fp32 -> bf16 hi/lo ----------------------------------
__global__ void split_kernel(const float* __restrict__ X,
                             __nv_bfloat16* __restrict__ H,
                             __nv_bfloat16* __restrict__ L, int n4)
{
    int i = blockIdx.x * blockDim.x + threadIdx.x;
    if (i >= n4) return;
    float4 v = ((const float4*)X)[i];
    __nv_bfloat16 h0 = __float2bfloat16(v.x), h1 = __float2bfloat16(v.y);
    __nv_bfloat16 h2 = __float2bfloat16(v.z), h3 = __float2bfloat16(v.w);
    __nv_bfloat16 l0 = __float2bfloat16(v.x - __bfloat162float(h0));
    __nv_bfloat16 l1 = __float2bfloat16(v.y - __bfloat162float(h1));
    __nv_bfloat16 l2 = __float2bfloat16(v.z - __bfloat162float(h2));
    __nv_bfloat16 l3 = __float2bfloat16(v.w - __bfloat162float(h3));
    __nv_bfloat162 hA = {h0, h1}, hB = {h2, h3}, lA = {l0, l1}, lB = {l2, l3};
    uint2 hv, lv;
    hv.x = *(uint32_t*)&hA; hv.y = *(uint32_t*)&hB;
    lv.x = *(uint32_t*)&lA; lv.y = *(uint32_t*)&lB;
    ((uint2*)H)[i] = hv;
    ((uint2*)L)[i] = lv;
}

// ---------------- HMMA split-bf16 GEMM: C = A @ B^T --------------------------
// A[M,K], B[N,K] bf16 hi/lo. 128x128 tile, BK=32, 8 warps (2x4), warp 64x32.
#define GSTRIDE 40                       // bf16 elems per smem row (32 + 8 pad)
#define GARR    (128 * GSTRIDE * 2)      // bytes per array tile (10240)
#define GBUF    (4 * GARR)               // bytes per stage (40960)
#define G_SMEM_SZ (2 * GBUF)             // 81920

__global__ __launch_bounds__(256, 1) void gemm_mma(
    const __nv_bfloat16* __restrict__ Ah, const __nv_bfloat16* __restrict__ Al,
    const __nv_bfloat16* __restrict__ Bh, const __nv_bfloat16* __restrict__ Bl,
    float* __restrict__ C, int M, int N, int K)
{
    extern __shared__ char smem[];
    const uint32_t sb = smem_u32(smem);
    const int tid = threadIdx.x;
    const int lane = tid & 31;
    const int wid = tid >> 5;
    const int warp_m = wid >> 2;     // 0..1 -> 64 rows
    const int warp_n = wid & 3;      // 0..3 -> 32 cols
    const int m0 = blockIdx.y * 128, n0 = blockIdx.x * 128;

    float acc[4][4][4] = {};

    const __nv_bfloat16* srcs[4] = {Ah, Al, Bh, Bl};

    // issue cp.async for one 32-wide K chunk into stage buf
    auto load_chunk = [&](int k0, int buf) {
        const uint32_t boff = sb + (uint32_t)buf * GBUF;
        #pragma unroll
        for (int p = 0; p < 4; ++p) {
            const __nv_bfloat16* src = srcs[p];
            const int r0 = (p < 2) ? m0 : n0;
            const uint32_t abase = boff + (uint32_t)p * GARR;
            #pragma unroll
            for (int t = 0; t < 2; ++t) {
                int u = tid + t * 256;
                int row = u >> 2, c = (u & 3) * 8;
                cp_async16(abase + (uint32_t)(row * GSTRIDE + c) * 2,
                           src + (size_t)(r0 + row) * K + k0 + c);
            }
        }
        asm volatile("cp.async.commit_group;" ::: "memory");
    };

    load_chunk(0, 0);

    const int nch = K / 32;
    for (int c = 0; c < nch; ++c) {
        if (c + 1 < nch) {
            load_chunk((c + 1) * 32, (c + 1) & 1);
            asm volatile("cp.async.wait_group 1;" ::: "memory");
        } else {
            asm volatile("cp.async.wait_group 0;" ::: "memory");
        }
        __syncthreads();

        const uint32_t boff = sb + (uint32_t)(c & 1) * GBUF;
        #pragma unroll
        for (int ks = 0; ks < 2; ++ks) {
            uint32_t ah[4][4], al[4][4], bh[4][2], bl[4][2];
            // A frags: 4 m16 tiles, hi + lo
            {
                const int arow = warp_m * 64 + (lane & 15);
                const int acol = ks * 16 + (lane >> 4) * 8;
                #pragma unroll
                for (int mi = 0; mi < 4; ++mi) {
                    uint32_t addr = boff + (uint32_t)((arow + mi * 16) * GSTRIDE + acol) * 2;
                    ldmx4(ah[mi], addr);
                    ldmx4(al[mi], addr + GARR);
                }
            }
            // B frags: 2 x4 loads cover 4 n8 tiles, hi + lo
            {
                const int brow_base = warp_n * 32 + ((lane >> 4) * 8) + (lane & 7);
                const int bcol = ks * 16 + ((lane >> 3) & 1) * 8;
                #pragma unroll
                for (int g = 0; g < 2; ++g) {
                    uint32_t addr = boff + 2 * GARR +
                                    (uint32_t)((brow_base + g * 16) * GSTRIDE + bcol) * 2;
                    uint32_t r[4];
                    ldmx4(r, addr);
                    bh[g * 2][0] = r[0]; bh[g * 2][1] = r[1];
                    bh[g * 2 + 1][0] = r[2]; bh[g * 2 + 1][1] = r[3];
                    ldmx4(r, addr + GARR);
                    bl[g * 2][0] = r[0]; bl[g * 2][1] = r[1];
                    bl[g * 2 + 1][0] = r[2]; bl[g * 2 + 1][1] = r[3];
                }
            }
            #pragma unroll
            for (int mi = 0; mi < 4; ++mi)
                #pragma unroll
                for (int ni = 0; ni < 4; ++ni) {
                    mma16816(acc[mi][ni], ah[mi], bh[ni]);
                    mma16816(acc[mi][ni], ah[mi], bl[ni]);
                    mma16816(acc[mi][ni], al[mi], bh[ni]);
                }
        }
        __syncthreads();
    }

    // epilogue: c frag -> C. thread holds (row=lane>>2, col=2*(lane&3)) and row+8.
    #pragma unroll
    for (int mi = 0; mi < 4; ++mi) {
        const int r = m0 + warp_m * 64 + mi * 16 + (lane >> 2);
        #pragma unroll
        for (int ni = 0; ni < 4; ++ni) {
            const int cidx = n0 + warp_n * 32 + ni * 8 + (lane & 3) * 2;
            float2 v0 = {acc[mi][ni][0], acc[mi][ni][1]};
            float2 v1 = {acc[mi][ni][2], acc[mi][ni][3]};
            *(float2*)(C + (size_t)r * N + cidx)       = v0;
            *(float2*)(C + (size_t)(r + 8) * N + cidx) = v1;
        }
    }
}

// ---------------- RoPE ------------------------------------------------------
__global__ void rope_kernel(float* __restrict__ Q, float* __restrict__ K, int npairs)
{
    int p = blockIdx.x * blockDim.x + threadIdx.x;
    if (p >= npairs) return;
    int row = p >> 9;
    int pr  = p & 511;
    int i   = pr & 31;
    int s   = row & (S_LEN - 1);
    float inv = expf(-logf(10000.0f) * ((float)i / 32.0f));
    float ang = (float)s * inv;
    float sn, cs;
    sincosf(ang, &sn, &cs);
    size_t idx = (size_t)row * D_MODEL + (size_t)(pr >> 5) * HDIM + 2 * i;
    float qe = Q[idx], qo = Q[idx + 1];
    Q[idx]     = qe * cs - qo * sn;
    Q[idx + 1] = qe * sn + qo * cs;
    float ke = K[idx], ko = K[idx + 1];
    K[idx]     = ke * cs - ko * sn;
    K[idx + 1] = ke * sn + ko * cs;
}

// ---------------- causal flash attention (fp32 SIMT) -------------------------
__global__ __launch_bounds__(256) void flash_kernel(
    const float* __restrict__ Qg, const float* __restrict__ Kg,
    const float* __restrict__ Vg, float* __restrict__ Og)
{
    extern __shared__ float sm[];
    float* Qt   = sm;
    float* Kt   = Qt + 64 * 132;
    float* Vs   = Kt + 64 * 68;
    float* Ss   = Vs + 64 * 68;
    float* rmax = Ss + 64 * 132;
    float* rsum = rmax + 128;
    float* ralp = rsum + 128;

    const int tid = threadIdx.x;
    const int b = blockIdx.z, h = blockIdx.y;
    const int q0 = blockIdx.x * 128;
    const int ty = tid >> 4;
    const int tx = tid & 15;

    const float* Qb = Qg + (size_t)(b * S_LEN + q0) * D_MODEL + h * HDIM;

    #pragma unroll
    for (int it = 0; it < 8; ++it) {
        int idx = tid + it * 256;
        int r = idx >> 4, c4 = (idx & 15) << 2;
        float4 v = *(const float4*)(Qb + (size_t)r * D_MODEL + c4);
        Qt[(c4 + 0) * 132 + r] = v.x;
        Qt[(c4 + 1) * 132 + r] = v.y;
        Qt[(c4 + 2) * 132 + r] = v.z;
        Qt[(c4 + 3) * 132 + r] = v.w;
    }
    if (tid < 128) { rmax[tid] = -1e30f; rsum[tid] = 0.0f; }

    float o[8][4] = {};
    const int jend = 2 * blockIdx.x + 2;

    for (int j = 0; j < jend; ++j) {
        const int k0 = j * 64;
        const float* Kb = Kg + (size_t)(b * S_LEN + k0) * D_MODEL + h * HDIM;
        const float* Vb = Vg + (size_t)(b * S_LEN + k0) * D_MODEL + h * HDIM;

        __syncthreads();
        #pragma unroll
        for (int it = 0; it < 4; ++it) {
            int idx = tid + it * 256;
            int r = idx >> 4, c4 = (idx & 15) << 2;
            float4 kv = *(const float4*)(Kb + (size_t)r * D_MODEL + c4);
            Kt[(c4 + 0) * 68 + r] = kv.x;
            Kt[(c4 + 1) * 68 + r] = kv.y;
            Kt[(c4 + 2) * 68 + r] = kv.z;
            Kt[(c4 + 3) * 68 + r] = kv.w;
            float4 vv = *(const float4*)(Vb + (size_t)r * D_MODEL + c4);
            *(float4*)&Vs[r * 68 + c4] = vv;
        }
        __syncthreads();

        float s[8][4] = {};
        #pragma unroll 8
        for (int kk = 0; kk < 64; ++kk) {
            float4 q0v = *(const float4*)&Qt[kk * 132 + ty * 8];
            float4 q1v = *(const float4*)&Qt[kk * 132 + ty * 8 + 4];
            float4 kv  = *(const float4*)&Kt[kk * 68  + tx * 4];
            float qv[8]  = {q0v.x, q0v.y, q0v.z, q0v.w, q1v.x, q1v.y, q1v.z, q1v.w};
            float kvv[4] = {kv.x, kv.y, kv.z, kv.w};
            #pragma unroll
            for (int i = 0; i < 8; ++i)
                #pragma unroll
                for (int jj = 0; jj < 4; ++jj)
                    s[i][jj] += qv[i] * kvv[jj];
        }

        const float scale = 0.125f;
        const bool need_mask = (k0 + 63 > q0);
        #pragma unroll
        for (int i = 0; i < 8; ++i) {
            #pragma unroll
            for (int jj = 0; jj < 4; ++jj) {
                float val = s[i][jj] * scale;
                if (need_mask && (k0 + tx * 4 + jj > q0 + ty * 8 + i)) val = -1e30f;
                Ss[(tx * 4 + jj) * 132 + ty * 8 + i] = val;
            }
        }
        __syncthreads();

        if (tid < 128) {
            int r = tid;
            float mo = rmax[r];
            float mt = -1e30f;
            for (int c = 0; c < 64; ++c) mt = fmaxf(mt, Ss[c * 132 + r]);
            float mn = fmaxf(mo, mt);
            float al = __expf(mo - mn);
            float ps = 0.0f;
            for (int c = 0; c < 64; ++c) {
                float pv = __expf(Ss[c * 132 + r] - mn);
                Ss[c * 132 + r] = pv;
                ps += pv;
            }
            rmax[r] = mn;
            rsum[r] = rsum[r] * al + ps;
            ralp[r] = al;
        }
        __syncthreads();

        #pragma unroll
        for (int i = 0; i < 8; ++i) {
            float al = ralp[ty * 8 + i];
            #pragma unroll
            for (int jj = 0; jj < 4; ++jj) o[i][jj] *= al;
        }
        #pragma unroll 8
        for (int kk = 0; kk < 64; ++kk) {
            float4 p0 = *(const float4*)&Ss[kk * 132 + ty * 8];
            float4 p1 = *(const float4*)&Ss[kk * 132 + ty * 8 + 4];
            float4 vv = *(const float4*)&Vs[kk * 68  + tx * 4];
            float pv[8]  = {p0.x, p0.y, p0.z, p0.w, p1.x, p1.y, p1.z, p1.w};
            float vvv[4] = {vv.x, vv.y, vv.z, vv.w};
            #pragma unroll
            for (int i = 0; i < 8; ++i)
                #pragma unroll
                for (int jj = 0; jj < 4; ++jj)
                    o[i][jj] += pv[i] * vvv[jj];
        }
    }

    float* Ob = Og + (size_t)(b * S_LEN + q0) * D_MODEL + h * HDIM;
    #pragma unroll
    for (int i = 0; i < 8; ++i) {
        float inv = 1.0f / rsum[ty * 8 + i];
        float4 w = {o[i][0] * inv, o[i][1] * inv, o[i][2] * inv, o[i][3] * inv};
        *(float4*)(Ob + (size_t)(ty * 8 + i) * D_MODEL + tx * 4) = w;
    }
}

// ---------------------------------------------------------------------------
extern "C" void kernel_launch(void* const* d_in, const int* in_sizes, int n_in,
                              void* d_out, int out_size)
{
    const float* x  = (const float*)d_in[0];
    const float* qw = (const float*)d_in[1];
    const float* kw = (const float*)d_in[2];
    const float* vw = (const float*)d_in[3];
    const float* ow = (const float*)d_in[4];

    const int M = in_sizes[0] / D_MODEL;   // B * S
    const int B = M / S_LEN;
    const int W = D_MODEL * D_MODEL;

    void *pq, *pk, *pv, *pa, *pxh, *pxl, *pah, *pal, *pwh, *pwl;
    cudaGetSymbolAddress(&pq, g_Q);   cudaGetSymbolAddress(&pk, g_K);
    cudaGetSymbolAddress(&pv, g_V);   cudaGetSymbolAddress(&pa, g_AO);
    cudaGetSymbolAddress(&pxh, g_xh); cudaGetSymbolAddress(&pxl, g_xl);
    cudaGetSymbolAddress(&pah, g_aoh); cudaGetSymbolAddress(&pal, g_aol);
    cudaGetSymbolAddress(&pwh, g_wh); cudaGetSymbolAddress(&pwl, g_wl);
    float* Qp = (float*)pq; float* Kp = (float*)pk;
    float* Vp = (float*)pv; float* AOp = (float*)pa;
    __nv_bfloat16* xh = (__nv_bfloat16*)pxh; __nv_bfloat16* xl = (__nv_bfloat16*)pxl;
    __nv_bfloat16* aoh = (__nv_bfloat16*)pah; __nv_bfloat16* aol = (__nv_bfloat16*)pal;
    __nv_bfloat16* wh = (__nv_bfloat16*)pwh; __nv_bfloat16* wl = (__nv_bfloat16*)pwl;

    int n4x = M * D_MODEL / 4;
    split_kernel<<<(n4x + 255) / 256, 256>>>(x, xh, xl, n4x);
    int n4w = W / 4;
    split_kernel<<<(n4w + 255) / 256, 256>>>(qw, wh + 0 * W, wl + 0 * W, n4w);
    split_kernel<<<(n4w + 255) / 256, 256>>>(kw, wh + 1 * W, wl + 1 * W, n4w);
    split_kernel<<<(n4w + 255) / 256, 256>>>(vw, wh + 2 * W, wl + 2 * W, n4w);
    split_kernel<<<(n4w + 255) / 256, 256>>>(ow, wh + 3 * W, wl + 3 * W, n4w);

    cudaFuncSetAttribute(gemm_mma, cudaFuncAttributeMaxDynamicSharedMemorySize, G_SMEM_SZ);
    dim3 ggrid(D_MODEL / 128, M / 128);
    gemm_mma<<<ggrid, 256, G_SMEM_SZ>>>(xh, xl, wh + 0 * W, wl + 0 * W, Qp, M, D_MODEL, D_MODEL);
    gemm_mma<<<ggrid, 256, G_SMEM_SZ>>>(xh, xl, wh + 1 * W, wl + 1 * W, Kp, M, D_MODEL, D_MODEL);
    gemm_mma<<<ggrid, 256, G_SMEM_SZ>>>(xh, xl, wh + 2 * W, wl + 2 * W, Vp, M, D_MODEL, D_MODEL);

    int npairs = M * (D_MODEL / 2);
    rope_kernel<<<(npairs + 255) / 256, 256>>>(Qp, Kp, npairs);

    const int FLASH_SMEM = (64 * 132 + 64 * 68 + 64 * 68 + 64 * 132 + 3 * 128) * 4;
    cudaFuncSetAttribute(flash_kernel, cudaFuncAttributeMaxDynamicSharedMemorySize, FLASH_SMEM);
    dim3 fgrid(S_LEN / 128, NHEAD, B);
    flash_kernel<<<fgrid, 256, FLASH_SMEM>>>(Qp, Kp, Vp, AOp);

    split_kernel<<<(n4x + 255) / 256, 256>>>(AOp, aoh, aol, n4x);
    gemm_mma<<<ggrid, 256, G_SMEM_SZ>>>(aoh, aol, wh + 3 * W, wl + 3 * W, (float*)d_out, M, D_MODEL, D_MODEL);
}

// round 4
// speedup vs baseline: 2.4588x; 1.6374x over previous
#include <cuda_runtime.h>
#include <cuda_bf16.h>
#include <math.h>
#include <stdint.h>

#define D_MODEL 1024
#define S_LEN   2048
#define NHEAD   16
#define HDIM    64
#define MAXB    4
#define MMAX    (MAXB * S_LEN)

// ---------------- scratch (__device__ globals; no allocs allowed) ----------
__device__ float g_Q [MMAX * D_MODEL];
__device__ float g_K [MMAX * D_MODEL];
__device__ float g_V [MMAX * D_MODEL];
__device__ float g_AO[MMAX * D_MODEL];
__device__ __nv_bfloat16 g_xh [MMAX * D_MODEL];
__device__ __nv_bfloat16 g_xl [MMAX * D_MODEL];
__device__ __nv_bfloat16 g_aoh[MMAX * D_MODEL];
__device__ __nv_bfloat16 g_aol[MMAX * D_MODEL];
__device__ __nv_bfloat16 g_wh [4 * D_MODEL * D_MODEL];
__device__ __nv_bfloat16 g_wl [4 * D_MODEL * D_MODEL];
__device__ __nv_bfloat16 g_qh [MMAX * D_MODEL];
__device__ __nv_bfloat16 g_ql [MMAX * D_MODEL];
__device__ __nv_bfloat16 g_kh [MMAX * D_MODEL];
__device__ __nv_bfloat16 g_kl [MMAX * D_MODEL];
__device__ __nv_bfloat16 g_vh [MMAX * D_MODEL];
__device__ __nv_bfloat16 g_vl [MMAX * D_MODEL];

// ---------------- helpers ----------------------------------------------------
__device__ __forceinline__ uint32_t smem_u32(const void* p) {
    uint32_t a;
    asm("{ .reg .u64 t; cvta.to.shared.u64 t, %1; cvt.u32.u64 %0, t; }" : "=r"(a) : "l"(p));
    return a;
}
__device__ __forceinline__ void cp_async16(uint32_t saddr, const void* gptr) {
    asm volatile("cp.async.cg.shared.global [%0], [%1], 16;" :: "r"(saddr), "l"(gptr));
}
__device__ __forceinline__ void ldmx4(uint32_t* r, uint32_t addr) {
    asm volatile("ldmatrix.sync.aligned.m8n8.x4.shared.b16 {%0,%1,%2,%3}, [%4];"
                 : "=r"(r[0]), "=r"(r[1]), "=r"(r[2]), "=r"(r[3]) : "r"(addr));
}
__device__ __forceinline__ void ldmx4t(uint32_t* r, uint32_t addr) {
    asm volatile("ldmatrix.sync.aligned.m8n8.x4.trans.shared.b16 {%0,%1,%2,%3}, [%4];"
                 : "=r"(r[0]), "=r"(r[1]), "=r"(r[2]), "=r"(r[3]) : "r"(addr));
}
__device__ __forceinline__ void mma16816(float* d, const uint32_t* a, const uint32_t* b) {
    asm volatile("mma.sync.aligned.m16n8k16.row.col.f32.bf16.bf16.f32 "
                 "{%0,%1,%2,%3}, {%4,%5,%6,%7}, {%8,%9}, {%0,%1,%2,%3};"
                 : "+f"(d[0]), "+f"(d[1]), "+f"(d[2]), "+f"(d[3])
                 : "r"(a[0]), "r"(a[1]), "r"(a[2]), "r"(a[3]), "r"(b[0]), "r"(b[1]));
}
__device__ __forceinline__ uint32_t pack_bf2(float a, float b) {
    __nv_bfloat162 v = __float22bfloat162_rn(make_float2(a, b));
    return *(uint32_t*)&v;
}

// ---------------- split fp32 -> bf16 hi/lo ----------------------------------
__global__ void split_kernel(const float* __restrict__ X,
                             __nv_bfloat16* __restrict__ H,
                             __nv_bfloat16* __restrict__ L, int n4)
{
    int i = blockIdx.x * blockDim.x + threadIdx.x;
    if (i >= n4) return;
    float4 v = ((const float4*)X)[i];
    __nv_bfloat16 h0 = __float2bfloat16(v.x), h1 = __float2bfloat16(v.y);
    __nv_bfloat16 h2 = __float2bfloat16(v.z), h3 = __float2bfloat16(v.w);
    __nv_bfloat16 l0 = __float2bfloat16(v.x - __bfloat162float(h0));
    __nv_bfloat16 l1 = __float2bfloat16(v.y - __bfloat162float(h1));
    __nv_bfloat16 l2 = __float2bfloat16(v.z - __bfloat162float(h2));
    __nv_bfloat16 l3 = __float2bfloat16(v.w - __bfloat162float(h3));
    __nv_bfloat162 hA = {h0, h1}, hB = {h2, h3}, lA = {l0, l1}, lB = {l2, l3};
    uint2 hv, lv;
    hv.x = *(uint32_t*)&hA; hv.y = *(uint32_t*)&hB;
    lv.x = *(uint32_t*)&lA; lv.y = *(uint32_t*)&lB;
    ((uint2*)H)[i] = hv;
    ((uint2*)L)[i] = lv;
}

// ---------------- fused RoPE + split (Q scaled by 1/8, exact pow2) ----------
__global__ void rope_split(const float* __restrict__ Q, const float* __restrict__ K,
                           __nv_bfloat16* __restrict__ Qh, __nv_bfloat16* __restrict__ Ql,
                           __nv_bfloat16* __restrict__ Kh, __nv_bfloat16* __restrict__ Kl,
                           int npairs)
{
    int p = blockIdx.x * blockDim.x + threadIdx.x;
    if (p >= npairs) return;
    int row = p >> 9;
    int pr  = p & 511;
    int i   = pr & 31;
    int s   = row & (S_LEN - 1);
    float inv = expf(-logf(10000.0f) * ((float)i / 32.0f));
    float ang = (float)s * inv;
    float sn, cs;
    sincosf(ang, &sn, &cs);
    size_t idx = (size_t)row * D_MODEL + (size_t)(pr >> 5) * HDIM + 2 * i;

    float qe = Q[idx], qo = Q[idx + 1];
    float q0 = (qe * cs - qo * sn) * 0.125f;
    float q1 = (qe * sn + qo * cs) * 0.125f;
    __nv_bfloat16 qh0 = __float2bfloat16(q0), qh1 = __float2bfloat16(q1);
    Qh[idx] = qh0; Qh[idx + 1] = qh1;
    Ql[idx]     = __float2bfloat16(q0 - __bfloat162float(qh0));
    Ql[idx + 1] = __float2bfloat16(q1 - __bfloat162float(qh1));

    float ke = K[idx], ko = K[idx + 1];
    float k0 = ke * cs - ko * sn;
    float k1 = ke * sn + ko * cs;
    __nv_bfloat16 kh0 = __float2bfloat16(k0), kh1 = __float2bfloat16(k1);
    Kh[idx] = kh0; Kh[idx + 1] = kh1;
    Kl[idx]     = __float2bfloat16(k0 - __bfloat162float(kh0));
    Kl[idx + 1] = __float2bfloat16(k1 - __bfloat162float(kh1));
}

// ---------------- HMMA split-bf16 GEMM: C = A @ B^T --------------------------
#define GSTRIDE 40
#define GARR    (128 * GSTRIDE * 2)
#define GBUF    (4 * GARR)
#define G_SMEM_SZ (2 * GBUF)

__global__ __launch_bounds__(256, 1) void gemm_mma(
    const __nv_bfloat16* __restrict__ Ah, const __nv_bfloat16* __restrict__ Al,
    const __nv_bfloat16* __restrict__ Bh, const __nv_bfloat16* __restrict__ Bl,
    float* __restrict__ C, int M, int N, int K)
{
    extern __shared__ char smem[];
    const uint32_t sb = smem_u32(smem);
    const int tid = threadIdx.x;
    const int lane = tid & 31;
    const int wid = tid >> 5;
    const int warp_m = wid >> 2;
    const int warp_n = wid & 3;
    const int m0 = blockIdx.y * 128, n0 = blockIdx.x * 128;

    float acc[4][4][4] = {};
    const __nv_bfloat16* srcs[4] = {Ah, Al, Bh, Bl};

    auto load_chunk = [&](int k0, int buf) {
        const uint32_t boff = sb + (uint32_t)buf * GBUF;
        #pragma unroll
        for (int p = 0; p < 4; ++p) {
            const __nv_bfloat16* src = srcs[p];
            const int r0 = (p < 2) ? m0 : n0;
            const uint32_t abase = boff + (uint32_t)p * GARR;
            #pragma unroll
            for (int t = 0; t < 2; ++t) {
                int u = tid + t * 256;
                int row = u >> 2, c = (u & 3) * 8;
                cp_async16(abase + (uint32_t)(row * GSTRIDE + c) * 2,
                           src + (size_t)(r0 + row) * K + k0 + c);
            }
        }
        asm volatile("cp.async.commit_group;" ::: "memory");
    };

    load_chunk(0, 0);

    const int nch = K / 32;
    for (int c = 0; c < nch; ++c) {
        if (c + 1 < nch) {
            load_chunk((c + 1) * 32, (c + 1) & 1);
            asm volatile("cp.async.wait_group 1;" ::: "memory");
        } else {
            asm volatile("cp.async.wait_group 0;" ::: "memory");
        }
        __syncthreads();

        const uint32_t boff = sb + (uint32_t)(c & 1) * GBUF;
        #pragma unroll
        for (int ks = 0; ks < 2; ++ks) {
            uint32_t ah[4][4], al[4][4], bh[4][2], bl[4][2];
            {
                const int arow = warp_m * 64 + (lane & 15);
                const int acol = ks * 16 + (lane >> 4) * 8;
                #pragma unroll
                for (int mi = 0; mi < 4; ++mi) {
                    uint32_t addr = boff + (uint32_t)((arow + mi * 16) * GSTRIDE + acol) * 2;
                    ldmx4(ah[mi], addr);
                    ldmx4(al[mi], addr + GARR);
                }
            }
            {
                const int brow_base = warp_n * 32 + ((lane >> 4) * 8) + (lane & 7);
                const int bcol = ks * 16 + ((lane >> 3) & 1) * 8;
                #pragma unroll
                for (int g = 0; g < 2; ++g) {
                    uint32_t addr = boff + 2 * GARR +
                                    (uint32_t)((brow_base + g * 16) * GSTRIDE + bcol) * 2;
                    uint32_t r[4];
                    ldmx4(r, addr);
                    bh[g * 2][0] = r[0]; bh[g * 2][1] = r[1];
                    bh[g * 2 + 1][0] = r[2]; bh[g * 2 + 1][1] = r[3];
                    ldmx4(r, addr + GARR);
                    bl[g * 2][0] = r[0]; bl[g * 2][1] = r[1];
                    bl[g * 2 + 1][0] = r[2]; bl[g * 2 + 1][1] = r[3];
                }
            }
            #pragma unroll
            for (int mi = 0; mi < 4; ++mi)
                #pragma unroll
                for (int ni = 0; ni < 4; ++ni) {
                    mma16816(acc[mi][ni], ah[mi], bh[ni]);
                    mma16816(acc[mi][ni], ah[mi], bl[ni]);
                    mma16816(acc[mi][ni], al[mi], bh[ni]);
                }
        }
        __syncthreads();
    }

    #pragma unroll
    for (int mi = 0; mi < 4; ++mi) {
        const int r = m0 + warp_m * 64 + mi * 16 + (lane >> 2);
        #pragma unroll
        for (int ni = 0; ni < 4; ++ni) {
            const int cidx = n0 + warp_n * 32 + ni * 8 + (lane & 3) * 2;
            float2 v0 = {acc[mi][ni][0], acc[mi][ni][1]};
            float2 v1 = {acc[mi][ni][2], acc[mi][ni][3]};
            *(float2*)(C + (size_t)r * N + cidx)       = v0;
            *(float2*)(C + (size_t)(r + 8) * N + cidx) = v1;
        }
    }
}

// ---------------- HMMA split-bf16 causal flash attention --------------------
// block = 128 q-rows x (b,h). 8 warps, warp = m16. KV tiles 64x64, double-buffered.
#define FSTR   72                     // bf16 elems per smem row (64 + 8 pad)
#define FARR   (64 * FSTR * 2)        // 9216 B per array
#define FSTAGE (4 * FARR)             // 36864 B: Kh,Kl,Vh,Vl
#define F_SMEM (2 * FSTAGE)           // 73728 B

__global__ __launch_bounds__(256, 1) void flash_mma(
    const __nv_bfloat16* __restrict__ Qh_, const __nv_bfloat16* __restrict__ Ql_,
    const __nv_bfloat16* __restrict__ Kh_, const __nv_bfloat16* __restrict__ Kl_,
    const __nv_bfloat16* __restrict__ Vh_, const __nv_bfloat16* __restrict__ Vl_,
    float* __restrict__ Og)
{
    extern __shared__ char smem[];
    const uint32_t sb = smem_u32(smem);
    const int tid = threadIdx.x, lane = tid & 31, w = tid >> 5;
    const int b = blockIdx.z, h = blockIdx.y, q0 = blockIdx.x * 128;

    const size_t base_q = (size_t)(b * S_LEN + q0) * D_MODEL + h * HDIM;

    // ---- stage Q (hi at sb, lo at +128*FSTR*2) and load frags
    #pragma unroll
    for (int t = 0; t < 4; ++t) {
        int idx = tid + t * 256;
        int r = idx >> 3, c = (idx & 7) * 8;
        cp_async16(sb + (uint32_t)(r * FSTR + c) * 2, Qh_ + base_q + (size_t)r * D_MODEL + c);
        cp_async16(sb + 128 * FSTR * 2 + (uint32_t)(r * FSTR + c) * 2,
                   Ql_ + base_q + (size_t)r * D_MODEL + c);
    }
    asm volatile("cp.async.commit_group;" ::: "memory");
    asm volatile("cp.async.wait_group 0;" ::: "memory");
    __syncthreads();

    uint32_t qh[4][4], ql[4][4];
    {
        const int row = w * 16 + (lane & 15);
        #pragma unroll
        for (int ks = 0; ks < 4; ++ks) {
            const int col = ks * 16 + (lane >> 4) * 8;
            uint32_t addr = sb + (uint32_t)(row * FSTR + col) * 2;
            ldmx4(qh[ks], addr);
            ldmx4(ql[ks], addr + 128 * FSTR * 2);
        }
    }
    __syncthreads();

    const __nv_bfloat16* kv_src[4] = {Kh_, Kl_, Vh_, Vl_};
    auto load_kv = [&](int j, int st) {
        const size_t gb = (size_t)(b * S_LEN + j * 64) * D_MODEL + h * HDIM;
        const uint32_t sbase = sb + (uint32_t)st * FSTAGE;
        #pragma unroll
        for (int p = 0; p < 4; ++p) {
            #pragma unroll
            for (int t = 0; t < 2; ++t) {
                int idx = tid + t * 256;
                int r = idx >> 3, c = (idx & 7) * 8;
                cp_async16(sbase + (uint32_t)p * FARR + (uint32_t)(r * FSTR + c) * 2,
                           kv_src[p] + gb + (size_t)r * D_MODEL + c);
            }
        }
        asm volatile("cp.async.commit_group;" ::: "memory");
    };

    float o[8][4] = {};
    float mrow0 = -1e30f, mrow1 = -1e30f;
    float lrow0 = 0.0f,   lrow1 = 0.0f;
    const int jend = 2 * blockIdx.x + 2;

    load_kv(0, 0);

    for (int j = 0; j < jend; ++j) {
        if (j + 1 < jend) {
            load_kv(j + 1, (j + 1) & 1);
            asm volatile("cp.async.wait_group 1;" ::: "memory");
        } else {
            asm volatile("cp.async.wait_group 0;" ::: "memory");
        }
        __syncthreads();

        const int k0 = j * 64;
        if (k0 <= q0 + w * 16 + 15) {          // skip fully-masked warp tiles
            const uint32_t sbase = sb + (uint32_t)(j & 1) * FSTAGE;

            // ---- S = Q @ K^T (split 3-term)
            float s[8][4] = {};
            #pragma unroll
            for (int ks = 0; ks < 4; ++ks) {
                uint32_t bh[8][2], bl[8][2];
                #pragma unroll
                for (int g = 0; g < 4; ++g) {
                    const int row = g * 16 + (lane >> 4) * 8 + (lane & 7);
                    const int col = ks * 16 + ((lane >> 3) & 1) * 8;
                    uint32_t addr = sbase + (uint32_t)(row * FSTR + col) * 2;
                    uint32_t r4[4];
                    ldmx4(r4, addr);
                    bh[2*g][0]=r4[0]; bh[2*g][1]=r4[1]; bh[2*g+1][0]=r4[2]; bh[2*g+1][1]=r4[3];
                    ldmx4(r4, addr + FARR);
                    bl[2*g][0]=r4[0]; bl[2*g][1]=r4[1]; bl[2*g+1][0]=r4[2]; bl[2*g+1][1]=r4[3];
                }
                #pragma unroll
                for (int n = 0; n < 8; ++n) {
                    mma16816(s[n], qh[ks], bh[n]);
                    mma16816(s[n], qh[ks], bl[n]);
                    mma16816(s[n], ql[ks], bh[n]);
                }
            }

            // ---- causal mask
            const int gr0 = q0 + w * 16 + (lane >> 2);
            if (k0 + 63 > q0 + w * 16) {
                #pragma unroll
                for (int t = 0; t < 8; ++t) {
                    int c = k0 + t * 8 + 2 * (lane & 3);
                    if (c     > gr0)     s[t][0] = -1e30f;
                    if (c + 1 > gr0)     s[t][1] = -1e30f;
                    if (c     > gr0 + 8) s[t][2] = -1e30f;
                    if (c + 1 > gr0 + 8) s[t][3] = -1e30f;
                }
            }

            // ---- online softmax (scale already folded into Q)
            float mx0 = -1e30f, mx1 = -1e30f;
            #pragma unroll
            for (int t = 0; t < 8; ++t) {
                mx0 = fmaxf(mx0, fmaxf(s[t][0], s[t][1]));
                mx1 = fmaxf(mx1, fmaxf(s[t][2], s[t][3]));
            }
            mx0 = fmaxf(mx0, __shfl_xor_sync(0xffffffffu, mx0, 1));
            mx0 = fmaxf(mx0, __shfl_xor_sync(0xffffffffu, mx0, 2));
            mx1 = fmaxf(mx1, __shfl_xor_sync(0xffffffffu, mx1, 1));
            mx1 = fmaxf(mx1, __shfl_xor_sync(0xffffffffu, mx1, 2));
            const float mn0 = fmaxf(mrow0, mx0), mn1 = fmaxf(mrow1, mx1);
            const float a0 = __expf(mrow0 - mn0), a1 = __expf(mrow1 - mn1);
            mrow0 = mn0; mrow1 = mn1;

            float ps0 = 0.0f, ps1 = 0.0f;
            uint32_t ph0[8], ph1[8], pl0[8], pl1[8];
            #pragma unroll
            for (int t = 0; t < 8; ++t) {
                float p0 = __expf(s[t][0] - mn0), p1 = __expf(s[t][1] - mn0);
                float p2 = __expf(s[t][2] - mn1), p3 = __expf(s[t][3] - mn1);
                ps0 += p0 + p1; ps1 += p2 + p3;
                __nv_bfloat162 h01 = __float22bfloat162_rn(make_float2(p0, p1));
                __nv_bfloat162 h23 = __float22bfloat162_rn(make_float2(p2, p3));
                ph0[t] = *(uint32_t*)&h01;
                ph1[t] = *(uint32_t*)&h23;
                pl0[t] = pack_bf2(p0 - __bfloat162float(h01.x), p1 - __bfloat162float(h01.y));
                pl1[t] = pack_bf2(p2 - __bfloat162float(h23.x), p3 - __bfloat162float(h23.y));
            }
            ps0 += __shfl_xor_sync(0xffffffffu, ps0, 1);
            ps0 += __shfl_xor_sync(0xffffffffu, ps0, 2);
            ps1 += __shfl_xor_sync(0xffffffffu, ps1, 1);
            ps1 += __shfl_xor_sync(0xffffffffu, ps1, 2);
            lrow0 = lrow0 * a0 + ps0;
            lrow1 = lrow1 * a1 + ps1;

            #pragma unroll
            for (int t = 0; t < 8; ++t) {
                o[t][0] *= a0; o[t][1] *= a0;
                o[t][2] *= a1; o[t][3] *= a1;
            }

            // ---- O += P @ V (split 3-term), V via ldmatrix.trans
            #pragma unroll
            for (int ks = 0; ks < 4; ++ks) {
                uint32_t bvh[8][2], bvl[8][2];
                #pragma unroll
                for (int g = 0; g < 4; ++g) {
                    const int row = ks * 16 + (lane & 15);
                    const int col = g * 16 + (lane >> 4) * 8;
                    uint32_t addr = sbase + 2u * FARR + (uint32_t)(row * FSTR + col) * 2;
                    uint32_t r4[4];
                    ldmx4t(r4, addr);
                    bvh[2*g][0]=r4[0]; bvh[2*g][1]=r4[1]; bvh[2*g+1][0]=r4[2]; bvh[2*g+1][1]=r4[3];
                    ldmx4t(r4, addr + FARR);
                    bvl[2*g][0]=r4[0]; bvl[2*g][1]=r4[1]; bvl[2*g+1][0]=r4[2]; bvl[2*g+1][1]=r4[3];
                }
                uint32_t pah[4] = {ph0[2*ks], ph1[2*ks], ph0[2*ks+1], ph1[2*ks+1]};
                uint32_t pal[4] = {pl0[2*ks], pl1[2*ks], pl0[2*ks+1], pl1[2*ks+1]};
                #pragma unroll
                for (int n = 0; n < 8; ++n) {
                    mma16816(o[n], pah, bvh[n]);
                    mma16816(o[n], pah, bvl[n]);
                    mma16816(o[n], pal, bvh[n]);
                }
            }
        }
        __syncthreads();
    }

    // ---- epilogue
    const float inv0 = 1.0f / lrow0, inv1 = 1.0f / lrow1;
    const int r0g = q0 + w * 16 + (lane >> 2);
    float* Ob = Og + (size_t)b * S_LEN * D_MODEL + h * HDIM;
    #pragma unroll
    for (int t = 0; t < 8; ++t) {
        const int c = t * 8 + 2 * (lane & 3);
        float2 v0 = {o[t][0] * inv0, o[t][1] * inv0};
        float2 v1 = {o[t][2] * inv1, o[t][3] * inv1};
        *(float2*)(Ob + (size_t)r0g * D_MODEL + c)       = v0;
        *(float2*)(Ob + (size_t)(r0g + 8) * D_MODEL + c) = v1;
    }
}

// ---------------------------------------------------------------------------
extern "C" void kernel_launch(void* const* d_in, const int* in_sizes, int n_in,
                              void* d_out, int out_size)
{
    const float* x  = (const float*)d_in[0];
    const float* qw = (const float*)d_in[1];
    const float* kw = (const float*)d_in[2];
    const float* vw = (const float*)d_in[3];
    const float* ow = (const float*)d_in[4];

    const int M = in_sizes[0] / D_MODEL;
    const int B = M / S_LEN;
    const int W = D_MODEL * D_MODEL;

    void *pq, *pk, *pv, *pa, *pxh, *pxl, *pah, *pal, *pwh, *pwl;
    void *pqh, *pql, *pkh, *pkl, *pvh, *pvl;
    cudaGetSymbolAddress(&pq, g_Q);    cudaGetSymbolAddress(&pk, g_K);
    cudaGetSymbolAddress(&pv, g_V);    cudaGetSymbolAddress(&pa, g_AO);
    cudaGetSymbolAddress(&pxh, g_xh);  cudaGetSymbolAddress(&pxl, g_xl);
    cudaGetSymbolAddress(&pah, g_aoh); cudaGetSymbolAddress(&pal, g_aol);
    cudaGetSymbolAddress(&pwh, g_wh);  cudaGetSymbolAddress(&pwl, g_wl);
    cudaGetSymbolAddress(&pqh, g_qh);  cudaGetSymbolAddress(&pql, g_ql);
    cudaGetSymbolAddress(&pkh, g_kh);  cudaGetSymbolAddress(&pkl, g_kl);
    cudaGetSymbolAddress(&pvh, g_vh);  cudaGetSymbolAddress(&pvl, g_vl);
    float* Qp = (float*)pq;  float* Kp = (float*)pk;
    float* Vp = (float*)pv;  float* AOp = (float*)pa;
    __nv_bfloat16* xh = (__nv_bfloat16*)pxh;  __nv_bfloat16* xl = (__nv_bfloat16*)pxl;
    __nv_bfloat16* aoh = (__nv_bfloat16*)pah; __nv_bfloat16* aol = (__nv_bfloat16*)pal;
    __nv_bfloat16* wh = (__nv_bfloat16*)pwh;  __nv_bfloat16* wl = (__nv_bfloat16*)pwl;
    __nv_bfloat16* qhp = (__nv_bfloat16*)pqh; __nv_bfloat16* qlp = (__nv_bfloat16*)pql;
    __nv_bfloat16* khp = (__nv_bfloat16*)pkh; __nv_bfloat16* klp = (__nv_bfloat16*)pkl;
    __nv_bfloat16* vhp = (__nv_bfloat16*)pvh; __nv_bfloat16* vlp = (__nv_bfloat16*)pvl;

    int n4x = M * D_MODEL / 4;
    split_kernel<<<(n4x + 255) / 256, 256>>>(x, xh, xl, n4x);
    int n4w = W / 4;
    split_kernel<<<(n4w + 255) / 256, 256>>>(qw, wh + 0 * W, wl + 0 * W, n4w);
    split_kernel<<<(n4w + 255) / 256, 256>>>(kw, wh + 1 * W, wl + 1 * W, n4w);
    split_kernel<<<(n4w + 255) / 256, 256>>>(vw, wh + 2 * W, wl + 2 * W, n4w);
    split_kernel<<<(n4w + 255) / 256, 256>>>(ow, wh + 3 * W, wl + 3 * W, n4w);

    cudaFuncSetAttribute(gemm_mma, cudaFuncAttributeMaxDynamicSharedMemorySize, G_SMEM_SZ);
    dim3 ggrid(D_MODEL / 128, M / 128);
    gemm_mma<<<ggrid, 256, G_SMEM_SZ>>>(xh, xl, wh + 0 * W, wl + 0 * W, Qp, M, D_MODEL, D_MODEL);
    gemm_mma<<<ggrid, 256, G_SMEM_SZ>>>(xh, xl, wh + 1 * W, wl + 1 * W, Kp, M, D_MODEL, D_MODEL);
    gemm_mma<<<ggrid, 256, G_SMEM_SZ>>>(xh, xl, wh + 2 * W, wl + 2 * W, Vp, M, D_MODEL, D_MODEL);

    int npairs = M * (D_MODEL / 2);
    rope_split<<<(npairs + 255) / 256, 256>>>(Qp, Kp, qhp, qlp, khp, klp, npairs);
    split_kernel<<<(n4x + 255) / 256, 256>>>(Vp, vhp, vlp, n4x);

    cudaFuncSetAttribute(flash_mma, cudaFuncAttributeMaxDynamicSharedMemorySize, F_SMEM);
    dim3 fgrid(S_LEN / 128, NHEAD, B);
    flash_mma<<<fgrid, 256, F_SMEM>>>(qhp, qlp, khp, klp, vhp, vlp, AOp);

    split_kernel<<<(n4x + 255) / 256, 256>>>(AOp, aoh, aol, n4x);
    gemm_mma<<<ggrid, 256, G_SMEM_SZ>>>(aoh, aol, wh + 3 * W, wl + 3 * W, (float*)d_out, M, D_MODEL, D_MODEL);
}

// round 5
// speedup vs baseline: 2.6984x; 1.0974x over previous
#include <cuda_runtime.h>
#include <cuda_bf16.h>
#include <math.h>
#include <stdint.h>

#define D_MODEL 1024
#define S_LEN   2048
#define NHEAD   16
#define HDIM    64
#define MAXB    4
#define MMAX    (MAXB * S_LEN)

// ---------------- scratch (__device__ globals; no allocs allowed) ----------
__device__ __nv_bfloat16 g_xh [MMAX * D_MODEL];
__device__ __nv_bfloat16 g_xl [MMAX * D_MODEL];
__device__ __nv_bfloat16 g_aoh[MMAX * D_MODEL];
__device__ __nv_bfloat16 g_aol[MMAX * D_MODEL];
__device__ __nv_bfloat16 g_wh [4 * D_MODEL * D_MODEL];
__device__ __nv_bfloat16 g_wl [4 * D_MODEL * D_MODEL];
__device__ __nv_bfloat16 g_qh [MMAX * D_MODEL];
__device__ __nv_bfloat16 g_ql [MMAX * D_MODEL];
__device__ __nv_bfloat16 g_kh [MMAX * D_MODEL];
__device__ __nv_bfloat16 g_kl [MMAX * D_MODEL];
__device__ __nv_bfloat16 g_vh [MMAX * D_MODEL];
__device__ __nv_bfloat16 g_vl [MMAX * D_MODEL];
__device__ float g_ct[S_LEN * 32];
__device__ float g_st[S_LEN * 32];

// ---------------- helpers ----------------------------------------------------
__device__ __forceinline__ uint32_t smem_u32(const void* p) {
    uint32_t a;
    asm("{ .reg .u64 t; cvta.to.shared.u64 t, %1; cvt.u32.u64 %0, t; }" : "=r"(a) : "l"(p));
    return a;
}
__device__ __forceinline__ void cp_async16(uint32_t saddr, const void* gptr) {
    asm volatile("cp.async.cg.shared.global [%0], [%1], 16;" :: "r"(saddr), "l"(gptr));
}
__device__ __forceinline__ void ldmx4(uint32_t* r, uint32_t addr) {
    asm volatile("ldmatrix.sync.aligned.m8n8.x4.shared.b16 {%0,%1,%2,%3}, [%4];"
                 : "=r"(r[0]), "=r"(r[1]), "=r"(r[2]), "=r"(r[3]) : "r"(addr));
}
__device__ __forceinline__ void ldmx4t(uint32_t* r, uint32_t addr) {
    asm volatile("ldmatrix.sync.aligned.m8n8.x4.trans.shared.b16 {%0,%1,%2,%3}, [%4];"
                 : "=r"(r[0]), "=r"(r[1]), "=r"(r[2]), "=r"(r[3]) : "r"(addr));
}
__device__ __forceinline__ void mma16816(float* d, const uint32_t* a, const uint32_t* b) {
    asm volatile("mma.sync.aligned.m16n8k16.row.col.f32.bf16.bf16.f32 "
                 "{%0,%1,%2,%3}, {%4,%5,%6,%7}, {%8,%9}, {%0,%1,%2,%3};"
                 : "+f"(d[0]), "+f"(d[1]), "+f"(d[2]), "+f"(d[3])
                 : "r"(a[0]), "r"(a[1]), "r"(a[2]), "r"(a[3]), "r"(b[0]), "r"(b[1]));
}
__device__ __forceinline__ void store_split_pair(
    __nv_bfloat16* H, __nv_bfloat16* L, size_t off, float a, float b)
{
    __nv_bfloat162 hi = __float22bfloat162_rn(make_float2(a, b));
    __nv_bfloat162 lo = __float22bfloat162_rn(
        make_float2(a - __bfloat162float(hi.x), b - __bfloat162float(hi.y)));
    *(__nv_bfloat162*)(H + off) = hi;
    *(__nv_bfloat162*)(L + off) = lo;
}

// ---------------- split fp32 -> bf16 hi/lo ----------------------------------
__global__ void split_kernel(const float* __restrict__ X,
                             __nv_bfloat16* __restrict__ H,
                             __nv_bfloat16* __restrict__ L, int n4)
{
    int i = blockIdx.x * blockDim.x + threadIdx.x;
    if (i >= n4) return;
    float4 v = ((const float4*)X)[i];
    __nv_bfloat16 h0 = __float2bfloat16(v.x), h1 = __float2bfloat16(v.y);
    __nv_bfloat16 h2 = __float2bfloat16(v.z), h3 = __float2bfloat16(v.w);
    __nv_bfloat16 l0 = __float2bfloat16(v.x - __bfloat162float(h0));
    __nv_bfloat16 l1 = __float2bfloat16(v.y - __bfloat162float(h1));
    __nv_bfloat16 l2 = __float2bfloat16(v.z - __bfloat162float(h2));
    __nv_bfloat16 l3 = __float2bfloat16(v.w - __bfloat162float(h3));
    __nv_bfloat162 hA = {h0, h1}, hB = {h2, h3}, lA = {l0, l1}, lB = {l2, l3};
    uint2 hv, lv;
    hv.x = *(uint32_t*)&hA; hv.y = *(uint32_t*)&hB;
    lv.x = *(uint32_t*)&lA; lv.y = *(uint32_t*)&lB;
    ((uint2*)H)[i] = hv;
    ((uint2*)L)[i] = lv;
}

// ---------------- RoPE cos/sin table ----------------------------------------
__global__ void rope_tab(float* __restrict__ ct, float* __restrict__ st)
{
    int idx = blockIdx.x * blockDim.x + threadIdx.x;
    if (idx >= S_LEN * 32) return;
    int s = idx >> 5, i = idx & 31;
    float inv = expf(-logf(10000.0f) * ((float)i / 32.0f));
    float sn, cs;
    sincosf((float)s * inv, &sn, &cs);
    ct[idx] = cs; st[idx] = sn;
}

// ---------------- fused QKV mega-GEMM (HMMA split-bf16 + rope/split epilogue)
#define GSTRIDE 40
#define GARR    (128 * GSTRIDE * 2)
#define GBUF    (4 * GARR)
#define G_SMEM_SZ (2 * GBUF)

__global__ __launch_bounds__(256, 1) void gemm_qkv(
    const __nv_bfloat16* __restrict__ Ah, const __nv_bfloat16* __restrict__ Al,
    const __nv_bfloat16* __restrict__ Wh, const __nv_bfloat16* __restrict__ Wl,
    __nv_bfloat16* __restrict__ Qh, __nv_bfloat16* __restrict__ Ql,
    __nv_bfloat16* __restrict__ Kh, __nv_bfloat16* __restrict__ Kl,
    __nv_bfloat16* __restrict__ Vh, __nv_bfloat16* __restrict__ Vl,
    const float* __restrict__ ct, const float* __restrict__ st,
    int M, int N, int K)
{
    extern __shared__ char smem[];
    const uint32_t sb = smem_u32(smem);
    const int tid = threadIdx.x;
    const int lane = tid & 31;
    const int wid = tid >> 5;
    const int warp_m = wid >> 2;
    const int warp_n = wid & 3;
    const int m0 = blockIdx.y * 128, n0 = blockIdx.x * 128;
    const int z = blockIdx.z;                       // 0=Q 1=K 2=V

    const __nv_bfloat16* Bh = Wh + (size_t)z * K * N;
    const __nv_bfloat16* Bl = Wl + (size_t)z * K * N;

    float acc[4][4][4] = {};
    const __nv_bfloat16* srcs[4] = {Ah, Al, Bh, Bl};

    auto load_chunk = [&](int k0, int buf) {
        const uint32_t boff = sb + (uint32_t)buf * GBUF;
        #pragma unroll
        for (int p = 0; p < 4; ++p) {
            const __nv_bfloat16* src = srcs[p];
            const int r0 = (p < 2) ? m0 : n0;
            const uint32_t abase = boff + (uint32_t)p * GARR;
            #pragma unroll
            for (int t = 0; t < 2; ++t) {
                int u = tid + t * 256;
                int row = u >> 2, c = (u & 3) * 8;
                cp_async16(abase + (uint32_t)(row * GSTRIDE + c) * 2,
                           src + (size_t)(r0 + row) * K + k0 + c);
            }
        }
        asm volatile("cp.async.commit_group;" ::: "memory");
    };

    load_chunk(0, 0);

    const int nch = K / 32;
    for (int c = 0; c < nch; ++c) {
        if (c + 1 < nch) {
            load_chunk((c + 1) * 32, (c + 1) & 1);
            asm volatile("cp.async.wait_group 1;" ::: "memory");
        } else {
            asm volatile("cp.async.wait_group 0;" ::: "memory");
        }
        __syncthreads();

        const uint32_t boff = sb + (uint32_t)(c & 1) * GBUF;
        #pragma unroll
        for (int ks = 0; ks < 2; ++ks) {
            uint32_t ah[4][4], al[4][4], bh[4][2], bl[4][2];
            {
                const int arow = warp_m * 64 + (lane & 15);
                const int acol = ks * 16 + (lane >> 4) * 8;
                #pragma unroll
                for (int mi = 0; mi < 4; ++mi) {
                    uint32_t addr = boff + (uint32_t)((arow + mi * 16) * GSTRIDE + acol) * 2;
                    ldmx4(ah[mi], addr);
                    ldmx4(al[mi], addr + GARR);
                }
            }
            {
                const int brow_base = warp_n * 32 + ((lane >> 4) * 8) + (lane & 7);
                const int bcol = ks * 16 + ((lane >> 3) & 1) * 8;
                #pragma unroll
                for (int g = 0; g < 2; ++g) {
                    uint32_t addr = boff + 2 * GARR +
                                    (uint32_t)((brow_base + g * 16) * GSTRIDE + bcol) * 2;
                    uint32_t r[4];
                    ldmx4(r, addr);
                    bh[g * 2][0] = r[0]; bh[g * 2][1] = r[1];
                    bh[g * 2 + 1][0] = r[2]; bh[g * 2 + 1][1] = r[3];
                    ldmx4(r, addr + GARR);
                    bl[g * 2][0] = r[0]; bl[g * 2][1] = r[1];
                    bl[g * 2 + 1][0] = r[2]; bl[g * 2 + 1][1] = r[3];
                }
            }
            #pragma unroll
            for (int mi = 0; mi < 4; ++mi)
                #pragma unroll
                for (int ni = 0; ni < 4; ++ni) {
                    mma16816(acc[mi][ni], ah[mi], bh[ni]);
                    mma16816(acc[mi][ni], ah[mi], bl[ni]);
                    mma16816(acc[mi][ni], al[mi], bh[ni]);
                }
        }
        __syncthreads();
    }

    // ---- epilogue: optional RoPE (+1/8 scale for Q), split to bf16 hi/lo
    __nv_bfloat16* H = (z == 0) ? Qh : (z == 1) ? Kh : Vh;
    __nv_bfloat16* L = (z == 0) ? Ql : (z == 1) ? Kl : Vl;
    const float qscale = (z == 0) ? 0.125f : 1.0f;

    #pragma unroll
    for (int mi = 0; mi < 4; ++mi) {
        const int r = m0 + warp_m * 64 + mi * 16 + (lane >> 2);
        const int s0 = r & (S_LEN - 1);
        const int s1 = (r + 8) & (S_LEN - 1);
        #pragma unroll
        for (int ni = 0; ni < 4; ++ni) {
            const int cidx = n0 + warp_n * 32 + ni * 8 + (lane & 3) * 2;  // even
            float a0 = acc[mi][ni][0], a1 = acc[mi][ni][1];
            float b0 = acc[mi][ni][2], b1 = acc[mi][ni][3];
            if (z < 2) {
                const int i = (cidx & (HDIM - 1)) >> 1;
                float c0 = ct[s0 * 32 + i], sn0 = st[s0 * 32 + i];
                float c1 = ct[s1 * 32 + i], sn1 = st[s1 * 32 + i];
                float e = a0, o = a1;
                a0 = (e * c0 - o * sn0) * qscale;
                a1 = (e * sn0 + o * c0) * qscale;
                e = b0; o = b1;
                b0 = (e * c1 - o * sn1) * qscale;
                b1 = (e * sn1 + o * c1) * qscale;
            }
            store_split_pair(H, L, (size_t)r * N + cidx, a0, a1);
            store_split_pair(H, L, (size_t)(r + 8) * N + cidx, b0, b1);
        }
    }
}

// ---------------- plain HMMA split-bf16 GEMM (final O-proj) ------------------
__global__ __launch_bounds__(256, 1) void gemm_mma(
    const __nv_bfloat16* __restrict__ Ah, const __nv_bfloat16* __restrict__ Al,
    const __nv_bfloat16* __restrict__ Bh, const __nv_bfloat16* __restrict__ Bl,
    float* __restrict__ C, int M, int N, int K)
{
    extern __shared__ char smem[];
    const uint32_t sb = smem_u32(smem);
    const int tid = threadIdx.x;
    const int lane = tid & 31;
    const int wid = tid >> 5;
    const int warp_m = wid >> 2;
    const int warp_n = wid & 3;
    const int m0 = blockIdx.y * 128, n0 = blockIdx.x * 128;

    float acc[4][4][4] = {};
    const __nv_bfloat16* srcs[4] = {Ah, Al, Bh, Bl};

    auto load_chunk = [&](int k0, int buf) {
        const uint32_t boff = sb + (uint32_t)buf * GBUF;
        #pragma unroll
        for (int p = 0; p < 4; ++p) {
            const __nv_bfloat16* src = srcs[p];
            const int r0 = (p < 2) ? m0 : n0;
            const uint32_t abase = boff + (uint32_t)p * GARR;
            #pragma unroll
            for (int t = 0; t < 2; ++t) {
                int u = tid + t * 256;
                int row = u >> 2, c = (u & 3) * 8;
                cp_async16(abase + (uint32_t)(row * GSTRIDE + c) * 2,
                           src + (size_t)(r0 + row) * K + k0 + c);
            }
        }
        asm volatile("cp.async.commit_group;" ::: "memory");
    };

    load_chunk(0, 0);

    const int nch = K / 32;
    for (int c = 0; c < nch; ++c) {
        if (c + 1 < nch) {
            load_chunk((c + 1) * 32, (c + 1) & 1);
            asm volatile("cp.async.wait_group 1;" ::: "memory");
        } else {
            asm volatile("cp.async.wait_group 0;" ::: "memory");
        }
        __syncthreads();

        const uint32_t boff = sb + (uint32_t)(c & 1) * GBUF;
        #pragma unroll
        for (int ks = 0; ks < 2; ++ks) {
            uint32_t ah[4][4], al[4][4], bh[4][2], bl[4][2];
            {
                const int arow = warp_m * 64 + (lane & 15);
                const int acol = ks * 16 + (lane >> 4) * 8;
                #pragma unroll
                for (int mi = 0; mi < 4; ++mi) {
                    uint32_t addr = boff + (uint32_t)((arow + mi * 16) * GSTRIDE + acol) * 2;
                    ldmx4(ah[mi], addr);
                    ldmx4(al[mi], addr + GARR);
                }
            }
            {
                const int brow_base = warp_n * 32 + ((lane >> 4) * 8) + (lane & 7);
                const int bcol = ks * 16 + ((lane >> 3) & 1) * 8;
                #pragma unroll
                for (int g = 0; g < 2; ++g) {
                    uint32_t addr = boff + 2 * GARR +
                                    (uint32_t)((brow_base + g * 16) * GSTRIDE + bcol) * 2;
                    uint32_t r[4];
                    ldmx4(r, addr);
                    bh[g * 2][0] = r[0]; bh[g * 2][1] = r[1];
                    bh[g * 2 + 1][0] = r[2]; bh[g * 2 + 1][1] = r[3];
                    ldmx4(r, addr + GARR);
                    bl[g * 2][0] = r[0]; bl[g * 2][1] = r[1];
                    bl[g * 2 + 1][0] = r[2]; bl[g * 2 + 1][1] = r[3];
                }
            }
            #pragma unroll
            for (int mi = 0; mi < 4; ++mi)
                #pragma unroll
                for (int ni = 0; ni < 4; ++ni) {
                    mma16816(acc[mi][ni], ah[mi], bh[ni]);
                    mma16816(acc[mi][ni], ah[mi], bl[ni]);
                    mma16816(acc[mi][ni], al[mi], bh[ni]);
                }
        }
        __syncthreads();
    }

    #pragma unroll
    for (int mi = 0; mi < 4; ++mi) {
        const int r = m0 + warp_m * 64 + mi * 16 + (lane >> 2);
        #pragma unroll
        for (int ni = 0; ni < 4; ++ni) {
            const int cidx = n0 + warp_n * 32 + ni * 8 + (lane & 3) * 2;
            float2 v0 = {acc[mi][ni][0], acc[mi][ni][1]};
            float2 v1 = {acc[mi][ni][2], acc[mi][ni][3]};
            *(float2*)(C + (size_t)r * N + cidx)       = v0;
            *(float2*)(C + (size_t)(r + 8) * N + cidx) = v1;
        }
    }
}

// ---------------- HMMA split-bf16 causal flash attention --------------------
#define FSTR   72
#define FARR   (64 * FSTR * 2)
#define FSTAGE (4 * FARR)
#define F_SMEM (2 * FSTAGE)

__global__ __launch_bounds__(256, 1) void flash_mma(
    const __nv_bfloat16* __restrict__ Qh_, const __nv_bfloat16* __restrict__ Ql_,
    const __nv_bfloat16* __restrict__ Kh_, const __nv_bfloat16* __restrict__ Kl_,
    const __nv_bfloat16* __restrict__ Vh_, const __nv_bfloat16* __restrict__ Vl_,
    __nv_bfloat16* __restrict__ AOh, __nv_bfloat16* __restrict__ AOl)
{
    extern __shared__ char smem[];
    const uint32_t sb = smem_u32(smem);
    const int tid = threadIdx.x, lane = tid & 31, w = tid >> 5;
    const int b = blockIdx.z, h = blockIdx.y, q0 = blockIdx.x * 128;

    const size_t base_q = (size_t)(b * S_LEN + q0) * D_MODEL + h * HDIM;

    #pragma unroll
    for (int t = 0; t < 4; ++t) {
        int idx = tid + t * 256;
        int r = idx >> 3, c = (idx & 7) * 8;
        cp_async16(sb + (uint32_t)(r * FSTR + c) * 2, Qh_ + base_q + (size_t)r * D_MODEL + c);
        cp_async16(sb + 128 * FSTR * 2 + (uint32_t)(r * FSTR + c) * 2,
                   Ql_ + base_q + (size_t)r * D_MODEL + c);
    }
    asm volatile("cp.async.commit_group;" ::: "memory");
    asm volatile("cp.async.wait_group 0;" ::: "memory");
    __syncthreads();

    uint32_t qh[4][4], ql[4][4];
    {
        const int row = w * 16 + (lane & 15);
        #pragma unroll
        for (int ks = 0; ks < 4; ++ks) {
            const int col = ks * 16 + (lane >> 4) * 8;
            uint32_t addr = sb + (uint32_t)(row * FSTR + col) * 2;
            ldmx4(qh[ks], addr);
            ldmx4(ql[ks], addr + 128 * FSTR * 2);
        }
    }
    __syncthreads();

    const __nv_bfloat16* kv_src[4] = {Kh_, Kl_, Vh_, Vl_};
    auto load_kv = [&](int j, int st) {
        const size_t gb = (size_t)(b * S_LEN + j * 64) * D_MODEL + h * HDIM;
        const uint32_t sbase = sb + (uint32_t)st * FSTAGE;
        #pragma unroll
        for (int p = 0; p < 4; ++p) {
            #pragma unroll
            for (int t = 0; t < 2; ++t) {
                int idx = tid + t * 256;
                int r = idx >> 3, c = (idx & 7) * 8;
                cp_async16(sbase + (uint32_t)p * FARR + (uint32_t)(r * FSTR + c) * 2,
                           kv_src[p] + gb + (size_t)r * D_MODEL + c);
            }
        }
        asm volatile("cp.async.commit_group;" ::: "memory");
    };

    float o[8][4] = {};
    float mrow0 = -1e30f, mrow1 = -1e30f;
    float lrow0 = 0.0f,   lrow1 = 0.0f;
    const int jend = 2 * blockIdx.x + 2;

    load_kv(0, 0);

    for (int j = 0; j < jend; ++j) {
        if (j + 1 < jend) {
            load_kv(j + 1, (j + 1) & 1);
            asm volatile("cp.async.wait_group 1;" ::: "memory");
        } else {
            asm volatile("cp.async.wait_group 0;" ::: "memory");
        }
        __syncthreads();

        const int k0 = j * 64;
        if (k0 <= q0 + w * 16 + 15) {
            const uint32_t sbase = sb + (uint32_t)(j & 1) * FSTAGE;

            // ---- S = Q @ K^T (3-term split)
            float s[8][4] = {};
            #pragma unroll
            for (int ks = 0; ks < 4; ++ks) {
                uint32_t bh[8][2], bl[8][2];
                #pragma unroll
                for (int g = 0; g < 4; ++g) {
                    const int row = g * 16 + (lane >> 4) * 8 + (lane & 7);
                    const int col = ks * 16 + ((lane >> 3) & 1) * 8;
                    uint32_t addr = sbase + (uint32_t)(row * FSTR + col) * 2;
                    uint32_t r4[4];
                    ldmx4(r4, addr);
                    bh[2*g][0]=r4[0]; bh[2*g][1]=r4[1]; bh[2*g+1][0]=r4[2]; bh[2*g+1][1]=r4[3];
                    ldmx4(r4, addr + FARR);
                    bl[2*g][0]=r4[0]; bl[2*g][1]=r4[1]; bl[2*g+1][0]=r4[2]; bl[2*g+1][1]=r4[3];
                }
                #pragma unroll
                for (int n = 0; n < 8; ++n) {
                    mma16816(s[n], qh[ks], bh[n]);
                    mma16816(s[n], qh[ks], bl[n]);
                    mma16816(s[n], ql[ks], bh[n]);
                }
            }

            // ---- causal mask
            const int gr0 = q0 + w * 16 + (lane >> 2);
            if (k0 + 63 > q0 + w * 16) {
                #pragma unroll
                for (int t = 0; t < 8; ++t) {
                    int c = k0 + t * 8 + 2 * (lane & 3);
                    if (c     > gr0)     s[t][0] = -1e30f;
                    if (c + 1 > gr0)     s[t][1] = -1e30f;
                    if (c     > gr0 + 8) s[t][2] = -1e30f;
                    if (c + 1 > gr0 + 8) s[t][3] = -1e30f;
                }
            }

            // ---- online softmax
            float mx0 = -1e30f, mx1 = -1e30f;
            #pragma unroll
            for (int t = 0; t < 8; ++t) {
                mx0 = fmaxf(mx0, fmaxf(s[t][0], s[t][1]));
                mx1 = fmaxf(mx1, fmaxf(s[t][2], s[t][3]));
            }
            mx0 = fmaxf(mx0, __shfl_xor_sync(0xffffffffu, mx0, 1));
            mx0 = fmaxf(mx0, __shfl_xor_sync(0xffffffffu, mx0, 2));
            mx1 = fmaxf(mx1, __shfl_xor_sync(0xffffffffu, mx1, 1));
            mx1 = fmaxf(mx1, __shfl_xor_sync(0xffffffffu, mx1, 2));
            const float mn0 = fmaxf(mrow0, mx0), mn1 = fmaxf(mrow1, mx1);
            const float a0 = __expf(mrow0 - mn0), a1 = __expf(mrow1 - mn1);
            mrow0 = mn0; mrow1 = mn1;

            float ps0 = 0.0f, ps1 = 0.0f;
            uint32_t ph0[8], ph1[8];
            #pragma unroll
            for (int t = 0; t < 8; ++t) {
                float p0 = __expf(s[t][0] - mn0), p1 = __expf(s[t][1] - mn0);
                float p2 = __expf(s[t][2] - mn1), p3 = __expf(s[t][3] - mn1);
                ps0 += p0 + p1; ps1 += p2 + p3;
                __nv_bfloat162 h01 = __float22bfloat162_rn(make_float2(p0, p1));
                __nv_bfloat162 h23 = __float22bfloat162_rn(make_float2(p2, p3));
                ph0[t] = *(uint32_t*)&h01;
                ph1[t] = *(uint32_t*)&h23;
            }
            ps0 += __shfl_xor_sync(0xffffffffu, ps0, 1);
            ps0 += __shfl_xor_sync(0xffffffffu, ps0, 2);
            ps1 += __shfl_xor_sync(0xffffffffu, ps1, 1);
            ps1 += __shfl_xor_sync(0xffffffffu, ps1, 2);
            lrow0 = lrow0 * a0 + ps0;
            lrow1 = lrow1 * a1 + ps1;

            #pragma unroll
            for (int t = 0; t < 8; ++t) {
                o[t][0] *= a0; o[t][1] *= a0;
                o[t][2] *= a1; o[t][3] *= a1;
            }

            // ---- O += Ph @ (Vh + Vl)   (P-lo term dropped; ~2e-4 rel err)
            #pragma unroll
            for (int ks = 0; ks < 4; ++ks) {
                uint32_t bvh[8][2], bvl[8][2];
                #pragma unroll
                for (int g = 0; g < 4; ++g) {
                    const int row = ks * 16 + (lane & 15);
                    const int col = g * 16 + (lane >> 4) * 8;
                    uint32_t addr = sbase + 2u * FARR + (uint32_t)(row * FSTR + col) * 2;
                    uint32_t r4[4];
                    ldmx4t(r4, addr);
                    bvh[2*g][0]=r4[0]; bvh[2*g][1]=r4[1]; bvh[2*g+1][0]=r4[2]; bvh[2*g+1][1]=r4[3];
                    ldmx4t(r4, addr + FARR);
                    bvl[2*g][0]=r4[0]; bvl[2*g][1]=r4[1]; bvl[2*g+1][0]=r4[2]; bvl[2*g+1][1]=r4[3];
                }
                uint32_t pah[4] = {ph0[2*ks], ph1[2*ks], ph0[2*ks+1], ph1[2*ks+1]};
                #pragma unroll
                for (int n = 0; n < 8; ++n) {
                    mma16816(o[n], pah, bvh[n]);
                    mma16816(o[n], pah, bvl[n]);
                }
            }
        }
        __syncthreads();
    }

    // ---- epilogue: normalize + split to bf16 hi/lo
    const float inv0 = 1.0f / lrow0, inv1 = 1.0f / lrow1;
    const int r0g = q0 + w * 16 + (lane >> 2);
    const size_t ob = (size_t)b * S_LEN * D_MODEL + h * HDIM;
    #pragma unroll
    for (int t = 0; t < 8; ++t) {
        const int c = t * 8 + 2 * (lane & 3);
        store_split_pair(AOh, AOl, ob + (size_t)r0g * D_MODEL + c,
                         o[t][0] * inv0, o[t][1] * inv0);
        store_split_pair(AOh, AOl, ob + (size_t)(r0g + 8) * D_MODEL + c,
                         o[t][2] * inv1, o[t][3] * inv1);
    }
}

// ---------------------------------------------------------------------------
extern "C" void kernel_launch(void* const* d_in, const int* in_sizes, int n_in,
                              void* d_out, int out_size)
{
    const float* x  = (const float*)d_in[0];
    const float* qw = (const float*)d_in[1];
    const float* kw = (const float*)d_in[2];
    const float* vw = (const float*)d_in[3];
    const float* ow = (const float*)d_in[4];

    const int M = in_sizes[0] / D_MODEL;
    const int B = M / S_LEN;
    const int W = D_MODEL * D_MODEL;

    void *pxh, *pxl, *pah, *pal, *pwh, *pwl;
    void *pqh, *pql, *pkh, *pkl, *pvh, *pvl, *pct, *pst;
    cudaGetSymbolAddress(&pxh, g_xh);  cudaGetSymbolAddress(&pxl, g_xl);
    cudaGetSymbolAddress(&pah, g_aoh); cudaGetSymbolAddress(&pal, g_aol);
    cudaGetSymbolAddress(&pwh, g_wh);  cudaGetSymbolAddress(&pwl, g_wl);
    cudaGetSymbolAddress(&pqh, g_qh);  cudaGetSymbolAddress(&pql, g_ql);
    cudaGetSymbolAddress(&pkh, g_kh);  cudaGetSymbolAddress(&pkl, g_kl);
    cudaGetSymbolAddress(&pvh, g_vh);  cudaGetSymbolAddress(&pvl, g_vl);
    cudaGetSymbolAddress(&pct, g_ct);  cudaGetSymbolAddress(&pst, g_st);
    __nv_bfloat16* xh = (__nv_bfloat16*)pxh;  __nv_bfloat16* xl = (__nv_bfloat16*)pxl;
    __nv_bfloat16* aoh = (__nv_bfloat16*)pah; __nv_bfloat16* aol = (__nv_bfloat16*)pal;
    __nv_bfloat16* wh = (__nv_bfloat16*)pwh;  __nv_bfloat16* wl = (__nv_bfloat16*)pwl;
    __nv_bfloat16* qhp = (__nv_bfloat16*)pqh; __nv_bfloat16* qlp = (__nv_bfloat16*)pql;
    __nv_bfloat16* khp = (__nv_bfloat16*)pkh; __nv_bfloat16* klp = (__nv_bfloat16*)pkl;
    __nv_bfloat16* vhp = (__nv_bfloat16*)pvh; __nv_bfloat16* vlp = (__nv_bfloat16*)pvl;
    float* ct = (float*)pct; float* st = (float*)pst;

    int n4x = M * D_MODEL / 4;
    split_kernel<<<(n4x + 255) / 256, 256>>>(x, xh, xl, n4x);
    int n4w = W / 4;
    split_kernel<<<(n4w + 255) / 256, 256>>>(qw, wh + 0 * W, wl + 0 * W, n4w);
    split_kernel<<<(n4w + 255) / 256, 256>>>(kw, wh + 1 * W, wl + 1 * W, n4w);
    split_kernel<<<(n4w + 255) / 256, 256>>>(vw, wh + 2 * W, wl + 2 * W, n4w);
    split_kernel<<<(n4w + 255) / 256, 256>>>(ow, wh + 3 * W, wl + 3 * W, n4w);
    rope_tab<<<(S_LEN * 32 + 255) / 256, 256>>>(ct, st);

    cudaFuncSetAttribute(gemm_qkv, cudaFuncAttributeMaxDynamicSharedMemorySize, G_SMEM_SZ);
    dim3 qkvgrid(D_MODEL / 128, M / 128, 3);
    gemm_qkv<<<qkvgrid, 256, G_SMEM_SZ>>>(xh, xl, wh, wl,
                                          qhp, qlp, khp, klp, vhp, vlp,
                                          ct, st, M, D_MODEL, D_MODEL);

    cudaFuncSetAttribute(flash_mma, cudaFuncAttributeMaxDynamicSharedMemorySize, F_SMEM);
    dim3 fgrid(S_LEN / 128, NHEAD, B);
    flash_mma<<<fgrid, 256, F_SMEM>>>(qhp, qlp, khp, klp, vhp, vlp, aoh, aol);

    cudaFuncSetAttribute(gemm_mma, cudaFuncAttributeMaxDynamicSharedMemorySize, G_SMEM_SZ);
    dim3 ggrid(D_MODEL / 128, M / 128);
    gemm_mma<<<ggrid, 256, G_SMEM_SZ>>>(aoh, aol, wh + 3 * W, wl + 3 * W,
                                        (float*)d_out, M, D_MODEL, D_MODEL);
}